// round 7
// baseline (speedup 1.0000x reference)
#include <cuda_runtime.h>

// Causal FIR: y[r][t] = sum_{k=0}^{15} b[k] * x[r][t-k], zero init per row.
// x: [64, 480000] f32, b: [16] f32, y: [64, 480000] f32.
//
// R5 ncu: L1 still binding (79.5%) — the 5 overlapping halo loads pay full
// wavefront + data-return cost even as L1 hits (5x read amplification).
//
// This version loads every input float exactly once (coalesced LDG.128) and
// builds each lane's 16-float causal halo from neighbor lanes' registers via
// rotated __shfl_sync + select. Each warp owns a chain of 5 consecutive
// 256-float tiles: the next tile's halo is the previous tile's registers,
// and the global halo load + tap loads happen once per chain. Next-tile
// loads are prefetched before computing the current tile to keep DRAM
// latency covered. L1 drops to ~0.06 wf/output; DRAM becomes the binder.

#define T_LEN    480000
#define NTAPS    16
#define BATCH    64
#define TILE     256                       // floats per warp tile (2 sub-panels)
#define N_TILES  (T_LEN / TILE)            // 1875 tiles per row
#define T_PER    5                         // tiles per warp chain
#define N_CHAIN  (N_TILES / T_PER)         // 375 chains per row
#define WARPS_PB 8
#define BLOCK    (WARPS_PB * 32)

__device__ __forceinline__ float4 shfl4(float4 v, int src) {
    float4 r;
    r.x = __shfl_sync(0xffffffffu, v.x, src);
    r.y = __shfl_sync(0xffffffffu, v.y, src);
    r.z = __shfl_sync(0xffffffffu, v.z, src);
    r.w = __shfl_sync(0xffffffffu, v.w, src);
    return r;
}

__global__ __launch_bounds__(BLOCK, 3)
void fir_apply_kernel(const float* __restrict__ x,
                      const float* __restrict__ b,
                      float* __restrict__ y)
{
    const int lane  = threadIdx.x & 31;
    const int warp  = threadIdx.x >> 5;
    const int chain = blockIdx.x * WARPS_PB + warp;
    if (chain >= N_CHAIN) return;            // warp-uniform exit
    const int row = blockIdx.y;

    const float4* __restrict__ x4 = reinterpret_cast<const float4*>(x + (size_t)row * T_LEN);
    float4* __restrict__ y4 = reinterpret_cast<float4*>(y + (size_t)row * T_LEN);

    // ---- taps (amortized over 5 tiles) ----
    float bb[NTAPS];
    {
        const float4* b4 = reinterpret_cast<const float4*>(b);
        float4 q0 = __ldg(b4 + 0), q1 = __ldg(b4 + 1),
               q2 = __ldg(b4 + 2), q3 = __ldg(b4 + 3);
        bb[0]  = q0.x; bb[1]  = q0.y; bb[2]  = q0.z; bb[3]  = q0.w;
        bb[4]  = q1.x; bb[5]  = q1.y; bb[6]  = q1.z; bb[7]  = q1.w;
        bb[8]  = q2.x; bb[9]  = q2.y; bb[10] = q2.z; bb[11] = q2.w;
        bb[12] = q3.x; bb[13] = q3.y; bb[14] = q3.z; bb[15] = q3.w;
    }

    int pb4 = chain * T_PER * (TILE / 4);    // float4 index of tile base

    // ---- halo for the first tile of the chain: lanes 28..31 hold
    // x[pb-16+4h .. pb-13+4h], h = lane-28. Chain 0 starts at t=0 -> zeros.
    float4 hv = make_float4(0.f, 0.f, 0.f, 0.f);
    if (chain > 0 && lane >= 28)
        hv = __ldg(x4 + (pb4 - 4 + (lane - 28)));

    // ---- preload first tile (coalesced: lane stride 16B) ----
    float4 v0 = __ldg(x4 + pb4 + lane);          // sub-panel 0
    float4 v1 = __ldg(x4 + pb4 + 32 + lane);     // sub-panel 1

    #pragma unroll 1
    for (int t = 0; t < T_PER; t++) {
        // prefetch next tile before computing (overlap DRAM latency)
        float4 nv0, nv1;
        if (t < T_PER - 1) {
            nv0 = __ldg(x4 + pb4 + 64 + lane);
            nv1 = __ldg(x4 + pb4 + 96 + lane);
        }

        // ---- assemble 20-float windows for both sub-panels via shfl ----
        // w[m] = x[t0 - 16 + m]; chain position (lane - d) via rotation.
        float w0[20], w1[20];
        #pragma unroll
        for (int d = 1; d <= 4; d++) {
            const int src = (lane - d) & 31;
            float4 r0 = shfl4(v0, src);          // v0 of lane-d  (wraps)
            float4 r1 = shfl4(v1, src);          // v1 of lane-d  (wraps)
            float4 hh = shfl4(hv, src);          // halo (lanes 28..31 valid)
            // sub-panel 0: lanes < d take halo; sub-panel 1: lanes < d take v0 wrap
            float4 W0, W1;
            W0.x = (lane >= d) ? r0.x : hh.x;  W1.x = (lane >= d) ? r1.x : r0.x;
            W0.y = (lane >= d) ? r0.y : hh.y;  W1.y = (lane >= d) ? r1.y : r0.y;
            W0.z = (lane >= d) ? r0.z : hh.z;  W1.z = (lane >= d) ? r1.z : r0.z;
            W0.w = (lane >= d) ? r0.w : hh.w;  W1.w = (lane >= d) ? r1.w : r0.w;
            const int m = 16 - 4 * d;
            w0[m+0] = W0.x; w0[m+1] = W0.y; w0[m+2] = W0.z; w0[m+3] = W0.w;
            w1[m+0] = W1.x; w1[m+1] = W1.y; w1[m+2] = W1.z; w1[m+3] = W1.w;
        }
        w0[16] = v0.x; w0[17] = v0.y; w0[18] = v0.z; w0[19] = v0.w;
        w1[16] = v1.x; w1[17] = v1.y; w1[18] = v1.z; w1[19] = v1.w;

        // ---- 8 independent FMA chains ----
        float a0 = 0.f, a1 = 0.f, a2 = 0.f, a3 = 0.f;
        float c0 = 0.f, c1 = 0.f, c2 = 0.f, c3 = 0.f;
        #pragma unroll
        for (int k = 0; k < NTAPS; k++) {
            a0 = fmaf(bb[k], w0[16 - k], a0);
            a1 = fmaf(bb[k], w0[17 - k], a1);
            a2 = fmaf(bb[k], w0[18 - k], a2);
            a3 = fmaf(bb[k], w0[19 - k], a3);
            c0 = fmaf(bb[k], w1[16 - k], c0);
            c1 = fmaf(bb[k], w1[17 - k], c1);
            c2 = fmaf(bb[k], w1[18 - k], c2);
            c3 = fmaf(bb[k], w1[19 - k], c3);
        }

        // ---- coalesced stores ----
        y4[pb4 + lane]      = make_float4(a0, a1, a2, a3);
        y4[pb4 + 32 + lane] = make_float4(c0, c1, c2, c3);

        // ---- slide the chain: next tile's halo = this tile's v1 ----
        hv = v1;
        v0 = nv0;
        v1 = nv1;
        pb4 += 64;
    }
}

extern "C" void kernel_launch(void* const* d_in, const int* in_sizes, int n_in,
                              void* d_out, int out_size)
{
    const float* x = (const float*)d_in[0];   // [64, 480000] f32
    const float* b = (const float*)d_in[1];   // [16] f32
    float* y = (float*)d_out;                 // [64, 480000] f32

    dim3 grid((N_CHAIN + WARPS_PB - 1) / WARPS_PB, BATCH, 1);   // (47, 64)
    fir_apply_kernel<<<grid, BLOCK>>>(x, b, y);
}

// round 8
// speedup vs baseline: 1.0430x; 1.0430x over previous
#include <cuda_runtime.h>

// Causal FIR: y[r][t] = sum_{k=0}^{15} b[k] * x[r][t-k], zero init per row.
// x: [64, 480000] f32, b: [16] f32, y: [64, 480000] f32.
//
// R5 ncu: L1 still binding (79.5%) — the 5 overlapping halo loads pay full
// wavefront + data-return cost even as L1 hits (5x read amplification).
//
// This version loads every input float exactly once (coalesced LDG.128) and
// builds each lane's 16-float causal halo from neighbor lanes' registers via
// rotated __shfl_sync + select. Each warp owns a chain of 5 consecutive
// 256-float tiles: the next tile's halo is the previous tile's registers,
// and the global halo load + tap loads happen once per chain. Next-tile
// loads are prefetched before computing the current tile to keep DRAM
// latency covered. L1 drops to ~0.06 wf/output; DRAM becomes the binder.

#define T_LEN    480000
#define NTAPS    16
#define BATCH    64
#define TILE     256                       // floats per warp tile (2 sub-panels)
#define N_TILES  (T_LEN / TILE)            // 1875 tiles per row
#define T_PER    5                         // tiles per warp chain
#define N_CHAIN  (N_TILES / T_PER)         // 375 chains per row
#define WARPS_PB 8
#define BLOCK    (WARPS_PB * 32)

__device__ __forceinline__ float4 shfl4(float4 v, int src) {
    float4 r;
    r.x = __shfl_sync(0xffffffffu, v.x, src);
    r.y = __shfl_sync(0xffffffffu, v.y, src);
    r.z = __shfl_sync(0xffffffffu, v.z, src);
    r.w = __shfl_sync(0xffffffffu, v.w, src);
    return r;
}

__global__ __launch_bounds__(BLOCK, 3)
void fir_apply_kernel(const float* __restrict__ x,
                      const float* __restrict__ b,
                      float* __restrict__ y)
{
    const int lane  = threadIdx.x & 31;
    const int warp  = threadIdx.x >> 5;
    const int chain = blockIdx.x * WARPS_PB + warp;
    if (chain >= N_CHAIN) return;            // warp-uniform exit
    const int row = blockIdx.y;

    const float4* __restrict__ x4 = reinterpret_cast<const float4*>(x + (size_t)row * T_LEN);
    float4* __restrict__ y4 = reinterpret_cast<float4*>(y + (size_t)row * T_LEN);

    // ---- taps (amortized over 5 tiles) ----
    float bb[NTAPS];
    {
        const float4* b4 = reinterpret_cast<const float4*>(b);
        float4 q0 = __ldg(b4 + 0), q1 = __ldg(b4 + 1),
               q2 = __ldg(b4 + 2), q3 = __ldg(b4 + 3);
        bb[0]  = q0.x; bb[1]  = q0.y; bb[2]  = q0.z; bb[3]  = q0.w;
        bb[4]  = q1.x; bb[5]  = q1.y; bb[6]  = q1.z; bb[7]  = q1.w;
        bb[8]  = q2.x; bb[9]  = q2.y; bb[10] = q2.z; bb[11] = q2.w;
        bb[12] = q3.x; bb[13] = q3.y; bb[14] = q3.z; bb[15] = q3.w;
    }

    int pb4 = chain * T_PER * (TILE / 4);    // float4 index of tile base

    // ---- halo for the first tile of the chain: lanes 28..31 hold
    // x[pb-16+4h .. pb-13+4h], h = lane-28. Chain 0 starts at t=0 -> zeros.
    float4 hv = make_float4(0.f, 0.f, 0.f, 0.f);
    if (chain > 0 && lane >= 28)
        hv = __ldg(x4 + (pb4 - 4 + (lane - 28)));

    // ---- preload first tile (coalesced: lane stride 16B) ----
    float4 v0 = __ldg(x4 + pb4 + lane);          // sub-panel 0
    float4 v1 = __ldg(x4 + pb4 + 32 + lane);     // sub-panel 1

    #pragma unroll 1
    for (int t = 0; t < T_PER; t++) {
        // prefetch next tile before computing (overlap DRAM latency)
        float4 nv0, nv1;
        if (t < T_PER - 1) {
            nv0 = __ldg(x4 + pb4 + 64 + lane);
            nv1 = __ldg(x4 + pb4 + 96 + lane);
        }

        // ---- assemble 20-float windows for both sub-panels via shfl ----
        // w[m] = x[t0 - 16 + m]; chain position (lane - d) via rotation.
        float w0[20], w1[20];
        #pragma unroll
        for (int d = 1; d <= 4; d++) {
            const int src = (lane - d) & 31;
            float4 r0 = shfl4(v0, src);          // v0 of lane-d  (wraps)
            float4 r1 = shfl4(v1, src);          // v1 of lane-d  (wraps)
            float4 hh = shfl4(hv, src);          // halo (lanes 28..31 valid)
            // sub-panel 0: lanes < d take halo; sub-panel 1: lanes < d take v0 wrap
            float4 W0, W1;
            W0.x = (lane >= d) ? r0.x : hh.x;  W1.x = (lane >= d) ? r1.x : r0.x;
            W0.y = (lane >= d) ? r0.y : hh.y;  W1.y = (lane >= d) ? r1.y : r0.y;
            W0.z = (lane >= d) ? r0.z : hh.z;  W1.z = (lane >= d) ? r1.z : r0.z;
            W0.w = (lane >= d) ? r0.w : hh.w;  W1.w = (lane >= d) ? r1.w : r0.w;
            const int m = 16 - 4 * d;
            w0[m+0] = W0.x; w0[m+1] = W0.y; w0[m+2] = W0.z; w0[m+3] = W0.w;
            w1[m+0] = W1.x; w1[m+1] = W1.y; w1[m+2] = W1.z; w1[m+3] = W1.w;
        }
        w0[16] = v0.x; w0[17] = v0.y; w0[18] = v0.z; w0[19] = v0.w;
        w1[16] = v1.x; w1[17] = v1.y; w1[18] = v1.z; w1[19] = v1.w;

        // ---- 8 independent FMA chains ----
        float a0 = 0.f, a1 = 0.f, a2 = 0.f, a3 = 0.f;
        float c0 = 0.f, c1 = 0.f, c2 = 0.f, c3 = 0.f;
        #pragma unroll
        for (int k = 0; k < NTAPS; k++) {
            a0 = fmaf(bb[k], w0[16 - k], a0);
            a1 = fmaf(bb[k], w0[17 - k], a1);
            a2 = fmaf(bb[k], w0[18 - k], a2);
            a3 = fmaf(bb[k], w0[19 - k], a3);
            c0 = fmaf(bb[k], w1[16 - k], c0);
            c1 = fmaf(bb[k], w1[17 - k], c1);
            c2 = fmaf(bb[k], w1[18 - k], c2);
            c3 = fmaf(bb[k], w1[19 - k], c3);
        }

        // ---- coalesced stores ----
        y4[pb4 + lane]      = make_float4(a0, a1, a2, a3);
        y4[pb4 + 32 + lane] = make_float4(c0, c1, c2, c3);

        // ---- slide the chain: next tile's halo = this tile's v1 ----
        hv = v1;
        v0 = nv0;
        v1 = nv1;
        pb4 += 64;
    }
}

extern "C" void kernel_launch(void* const* d_in, const int* in_sizes, int n_in,
                              void* d_out, int out_size)
{
    const float* x = (const float*)d_in[0];   // [64, 480000] f32
    const float* b = (const float*)d_in[1];   // [16] f32
    float* y = (float*)d_out;                 // [64, 480000] f32

    dim3 grid((N_CHAIN + WARPS_PB - 1) / WARPS_PB, BATCH, 1);   // (47, 64)
    fir_apply_kernel<<<grid, BLOCK>>>(x, b, y);
}